// round 16
// baseline (speedup 1.0000x reference)
#include <cuda_runtime.h>
#include <cuda_fp16.h>
#include <cstdint>

#define NN 100000
#define NE 1200000
#define SCAN_B 98   // ceil(NN / 1024)
#define NGROUP (NN / 4)   // 4-node gather groups

// ---------------- device scratch (no allocations allowed) ----------------
__device__ int                g_cnt[NN];
__device__ float              g_dinv[NN];
__device__ int                g_rowptr[NN + 1];
__device__ unsigned short     g_rank16[NE];
__device__ int                g_col[NE];
__device__ unsigned long long g_bval[SCAN_B];
__device__ unsigned           g_tick[2];      // gather work-stealing tickets
__device__ __half             g_bufh[NN * 64];
__device__ __half             g_buf2[NN * 64];

// HMMA m16n8k16 row.col f32 accumulate
#define MMA_16816(c0, c1, c2, c3, a0, a1, a2, a3, b0, b1) \
    asm volatile("mma.sync.aligned.m16n8k16.row.col.f32.f16.f16.f32 " \
        "{%0,%1,%2,%3}, {%4,%5,%6,%7}, {%8,%9}, {%0,%1,%2,%3};" \
        : "+f"(c0), "+f"(c1), "+f"(c2), "+f"(c3) \
        : "r"(a0), "r"(a1), "r"(a2), "r"(a3), "r"(b0), "r"(b1))

// ---------------- per-block dtype probe ----------------
__device__ __forceinline__ int probe_is64(const int* __restrict__ raw) {
    __shared__ int s_is64;
    if (threadIdx.x < 32) {
        bool ok = true;
#pragma unroll
        for (int k = 0; k < 4; k++) {
            int idx = threadIdx.x * 4 + k;
            ok &= (raw[2 * idx + 1] == 0) && ((unsigned)raw[2 * idx] < NN);
        }
        unsigned m = __ballot_sync(~0u, ok);
        if (threadIdx.x == 0) s_is64 = (m == ~0u) ? 1 : 0;
    }
    __syncthreads();
    return s_is64;
}

// load 4 consecutive edges [4*e4 .. 4*e4+3] from stream at word base
__device__ __forceinline__ int4 edge_quad(const int* __restrict__ raw,
                                          long long base, int e4, int is64) {
    if (is64) {
        const long long* p = (const long long*)raw + base + 4 * e4;
        longlong2 v0 = __ldg((const longlong2*)p);
        longlong2 v1 = __ldg((const longlong2*)(p + 2));
        return make_int4((int)v0.x, (int)v0.y, (int)v1.x, (int)v1.y);
    }
    return __ldg((const int4*)(raw + base + 4 * e4));
}

// ---------------- count + rank: 4 edges per thread ----------------
__global__ void k_count(const int* __restrict__ raw) {
    int is64 = probe_is64(raw);
    int e4 = blockIdx.x * blockDim.x + threadIdx.x;
    if (e4 >= NE / 4) return;
    int4 d = edge_quad(raw, NE, e4, is64);
    unsigned r0 = 0, r1 = 0, r2 = 0, r3 = 0;
    if ((unsigned)d.x < NN) r0 = (unsigned)atomicAdd(&g_cnt[d.x], 1);
    if ((unsigned)d.y < NN) r1 = (unsigned)atomicAdd(&g_cnt[d.y], 1);
    if ((unsigned)d.z < NN) r2 = (unsigned)atomicAdd(&g_cnt[d.z], 1);
    if ((unsigned)d.w < NN) r3 = (unsigned)atomicAdd(&g_cnt[d.w], 1);
    ((uint2*)g_rank16)[e4] = make_uint2((r0 & 0xFFFFu) | (r1 << 16),
                                        (r2 & 0xFFFFu) | (r3 << 16));
}

// ---------------- single-kernel scan (decoupled lookback) ----------------
__global__ void __launch_bounds__(1024) k_scan() {
    __shared__ int wsum[32];
    __shared__ int s_boff;
    int tid = threadIdx.x;
    int lane = tid & 31, wid = tid >> 5;
    int i = blockIdx.x * 1024 + tid;
    int c = (i < NN) ? g_cnt[i] : 0;
    if (i < NN) {
        g_dinv[i] = rsqrtf((float)c + 1.0f);
        g_cnt[i] = 0;
    }
    if (blockIdx.x == 0 && tid < 2) g_tick[tid] = 0;   // reset gather tickets
    int incl = c;
#pragma unroll
    for (int o = 1; o < 32; o <<= 1) {
        int t = __shfl_up_sync(~0u, incl, o);
        if (lane >= o) incl += t;
    }
    if (lane == 31) wsum[wid] = incl;
    __syncthreads();
    if (tid < 32) {
        int w = wsum[tid];
        int iw = w;
#pragma unroll
        for (int o = 1; o < 32; o <<= 1) {
            int t = __shfl_up_sync(~0u, iw, o);
            if (tid >= o) iw += t;
        }
        wsum[tid] = iw - w;
        if (tid == 31)
            atomicExch(&g_bval[blockIdx.x], (1ull << 32) | (unsigned)iw);
    }
    __syncthreads();
    if (wid == 0) {
        int my = blockIdx.x;
        unsigned acc = 0;
        for (int base = 0; base < my; base += 32) {
            int j = base + lane;
            if (j < my) {
                unsigned long long v;
                do { v = atomicAdd(&g_bval[j], 0ull); } while ((v >> 32) == 0);
                acc += (unsigned)v;
            }
        }
#pragma unroll
        for (int o = 16; o; o >>= 1) acc += __shfl_down_sync(~0u, acc, o);
        if (lane == 0) s_boff = (int)acc;
    }
    __syncthreads();
    if (i < NN) g_rowptr[i] = incl - c + wsum[wid] + s_boff;
    if (blockIdx.x == 0 && tid == 0) g_rowptr[NN] = NE;
}

// ---------------- fill CSR: 4 edges per thread, atomic-free ----------------
__global__ void k_fill(const int* __restrict__ raw) {
    int is64 = probe_is64(raw);
    if (blockIdx.x == 0 && threadIdx.x < SCAN_B) g_bval[threadIdx.x] = 0ull;
    int e4 = blockIdx.x * blockDim.x + threadIdx.x;
    if (e4 >= NE / 4) return;
    int4 s = edge_quad(raw, 0, e4, is64);
    int4 d = edge_quad(raw, NE, e4, is64);
    uint2 rr = ((const uint2*)g_rank16)[e4];
    if ((unsigned)s.x < NN && (unsigned)d.x < NN)
        g_col[g_rowptr[d.x] + (int)(rr.x & 0xFFFFu)] = s.x;
    if ((unsigned)s.y < NN && (unsigned)d.y < NN)
        g_col[g_rowptr[d.y] + (int)(rr.x >> 16)] = s.y;
    if ((unsigned)s.z < NN && (unsigned)d.z < NN)
        g_col[g_rowptr[d.z] + (int)(rr.y & 0xFFFFu)] = s.z;
    if ((unsigned)s.w < NN && (unsigned)d.w < NN)
        g_col[g_rowptr[d.w] + (int)(rr.y >> 16)] = s.w;
}

// ---------------- HMMA GEMM: out[N,NC] = X[N,64] @ W[64,NC] ----------------
template <int NC, typename InT, typename OutT, bool BIAS, bool SCALE>
__global__ void __launch_bounds__(256) k_gemm_mma(const InT* __restrict__ in,
                                                  const float* __restrict__ W,
                                                  const float* __restrict__ bias,
                                                  OutT* __restrict__ out) {
    constexpr int NT = NC / 8;
    constexpr int XS = 36;
    __shared__ uint32_t Bf[4][NT][32][2];
    __shared__ uint32_t Xs[128 * XS];

    int tid = threadIdx.x;
    int wid = tid >> 5, lane = tid & 31;
    int grp = lane >> 2;
    int q   = lane & 3;

    for (int i = tid; i < 4 * NT * 32 * 2; i += 256) {
        int reg = i & 1;
        int ln  = (i >> 1) & 31;
        int nt  = (i >> 6) % NT;
        int kt  = (i >> 6) / NT;
        int k0 = kt * 16 + (ln & 3) * 2 + reg * 8;
        int n  = nt * 8 + (ln >> 2);
        __half2 h = __floats2half2_rn(W[k0 * NC + n], W[(k0 + 1) * NC + n]);
        Bf[kt][nt][ln][reg] = *(uint32_t*)&h;
    }

    int ntiles = (NN + 127) / 128;
    for (int tile = blockIdx.x; tile < ntiles; tile += gridDim.x) {
        int row0 = tile * 128;
        __syncthreads();
        for (int i = tid; i < 128 * 32; i += 256) {
            int r = i >> 5, c = i & 31;
            uint32_t v = 0;
            if (row0 + r < NN) {
                if constexpr (sizeof(InT) == 4) {
                    float2 f = __ldg((const float2*)in + (size_t)(row0 + r) * 32 + c);
                    __half2 h = __floats2half2_rn(f.x, f.y);
                    v = *(uint32_t*)&h;
                } else {
                    v = __ldg((const uint32_t*)in + (size_t)(row0 + r) * 32 + c);
                }
            }
            Xs[r * XS + c] = v;
        }
        __syncthreads();

        int rb = wid * 16;
        float acc[NT][4];
#pragma unroll
        for (int nt = 0; nt < NT; nt++)
#pragma unroll
            for (int c = 0; c < 4; c++) acc[nt][c] = 0.f;

#pragma unroll
        for (int kt = 0; kt < 4; kt++) {
            uint32_t a0 = Xs[(rb + grp) * XS + kt * 8 + q];
            uint32_t a1 = Xs[(rb + grp + 8) * XS + kt * 8 + q];
            uint32_t a2 = Xs[(rb + grp) * XS + kt * 8 + 4 + q];
            uint32_t a3 = Xs[(rb + grp + 8) * XS + kt * 8 + 4 + q];
#pragma unroll
            for (int nt = 0; nt < NT; nt++) {
                uint32_t b0 = Bf[kt][nt][lane][0];
                uint32_t b1 = Bf[kt][nt][lane][1];
                MMA_16816(acc[nt][0], acc[nt][1], acc[nt][2], acc[nt][3],
                          a0, a1, a2, a3, b0, b1);
            }
        }

        int r0 = row0 + rb + grp;
        int r1 = r0 + 8;
        if constexpr (NC == 64) {
            float dv0 = (r0 < NN) ? __ldg(&g_dinv[r0]) : 0.f;
            float dv1 = (r1 < NN) ? __ldg(&g_dinv[r1]) : 0.f;
            if (!SCALE) { dv0 = 1.f; dv1 = 1.f; }
#pragma unroll
            for (int nt = 0; nt < NT; nt++) {
                int col = nt * 8 + q * 2;
                if (r0 < NN)
                    *(__half2*)((__half*)out + (size_t)r0 * NC + col) =
                        __floats2half2_rn(acc[nt][0] * dv0, acc[nt][1] * dv0);
                if (r1 < NN)
                    *(__half2*)((__half*)out + (size_t)r1 * NC + col) =
                        __floats2half2_rn(acc[nt][2] * dv1, acc[nt][3] * dv1);
            }
        } else {
#pragma unroll
            for (int nt = 0; nt < NT; nt++) {
                int col = nt * 8 + q * 2;
                float b0v = 0.f, b1v = 0.f;
                if (BIAS) { b0v = __ldg(&bias[col]); b1v = __ldg(&bias[col + 1]); }
                if (r0 < NN)
                    *(float2*)((float*)out + (size_t)r0 * NC + col) =
                        make_float2(acc[nt][0] + b0v, acc[nt][1] + b1v);
                if (r1 < NN)
                    *(float2*)((float*)out + (size_t)r1 * NC + col) =
                        make_float2(acc[nt][2] + b0v, acc[nt][3] + b1v);
            }
        }
    }
}

// ---------------- gather: work-stealing, 4 nodes/group, 8 lanes x 8 dims --------
__global__ void __launch_bounds__(256) k_gather(const uint4* __restrict__ hw,
                                                const float* __restrict__ bias,
                                                uint4* __restrict__ hout,
                                                int which) {
    int lane = threadIdx.x & 31;
    int sub  = lane & 7;
    float4 bl = ((const float4*)bias)[2 * sub];
    float4 bh = ((const float4*)bias)[2 * sub + 1];

    for (;;) {
        unsigned grp;
        if (lane == 0) grp = atomicAdd(&g_tick[which], 1u);
        grp = __shfl_sync(~0u, grp, 0);
        if (grp >= NGROUP) return;

        int node = grp * 4 + (lane >> 3);

        uint4 sv = __ldg(&hw[node * 8 + sub]);
        float2 s0 = __half22float2(*(__half2*)&sv.x);
        float2 s1 = __half22float2(*(__half2*)&sv.y);
        float2 s2 = __half22float2(*(__half2*)&sv.z);
        float2 s3 = __half22float2(*(__half2*)&sv.w);
        float a0 = s0.x, a1 = s0.y, a2 = s1.x, a3 = s1.y;
        float a4 = s2.x, a5 = s2.y, a6 = s3.x, a7 = s3.y;

        int j   = g_rowptr[node];
        int end = g_rowptr[node + 1];
        while (__any_sync(~0u, j < end)) {
#pragma unroll
            for (int k = 0; k < 4; k++) {
                bool act = j < end;
                int jj = act ? j : 0;
                int c = __ldg(&g_col[jj]);
                float m = act ? 1.0f : 0.0f;
                uint4 u = __ldg(&hw[c * 8 + sub]);
                float2 g0 = __half22float2(*(__half2*)&u.x);
                float2 g1 = __half22float2(*(__half2*)&u.y);
                float2 g2 = __half22float2(*(__half2*)&u.z);
                float2 g3 = __half22float2(*(__half2*)&u.w);
                a0 = fmaf(m, g0.x, a0); a1 = fmaf(m, g0.y, a1);
                a2 = fmaf(m, g1.x, a2); a3 = fmaf(m, g1.y, a3);
                a4 = fmaf(m, g2.x, a4); a5 = fmaf(m, g2.y, a5);
                a6 = fmaf(m, g3.x, a6); a7 = fmaf(m, g3.y, a7);
                j++;
            }
        }

        float dv = __ldg(&g_dinv[node]);
        float b0 = fmaxf(fmaf(a0, dv, bl.x), 0.f);
        float b1v = fmaxf(fmaf(a1, dv, bl.y), 0.f);
        float b2 = fmaxf(fmaf(a2, dv, bl.z), 0.f);
        float b3 = fmaxf(fmaf(a3, dv, bl.w), 0.f);
        float b4v = fmaxf(fmaf(a4, dv, bh.x), 0.f);
        float b5 = fmaxf(fmaf(a5, dv, bh.y), 0.f);
        float b6 = fmaxf(fmaf(a6, dv, bh.z), 0.f);
        float b7 = fmaxf(fmaf(a7, dv, bh.w), 0.f);
        uint4 o;
        *(__half2*)&o.x = __floats2half2_rn(b0, b1v);
        *(__half2*)&o.y = __floats2half2_rn(b2, b3);
        *(__half2*)&o.z = __floats2half2_rn(b4v, b5);
        *(__half2*)&o.w = __floats2half2_rn(b6, b7);
        hout[node * 8 + sub] = o;
    }
}

// ---------------- launch ----------------
extern "C" void kernel_launch(void* const* d_in, const int* in_sizes, int n_in,
                              void* d_out, int out_size) {
    const float* x  = (const float*)d_in[0];
    const int*   ei = (const int*)d_in[1];
    const float* W1 = (const float*)d_in[2];
    const float* b1 = (const float*)d_in[3];
    const float* W2 = (const float*)d_in[4];
    const float* b2 = (const float*)d_in[5];
    const float* Wl = (const float*)d_in[6];
    const float* bl = (const float*)d_in[7];
    float*       out = (float*)d_out;

    __half* bufh; cudaGetSymbolAddress((void**)&bufh, g_bufh);
    __half* buf2; cudaGetSymbolAddress((void**)&buf2, g_buf2);

    static cudaStream_t s2 = nullptr;
    static cudaEvent_t evS = nullptr, evJ = nullptr;
    if (s2 == nullptr) {
        cudaStreamCreateWithFlags(&s2, cudaStreamNonBlocking);
        cudaEventCreateWithFlags(&evS, cudaEventDisableTiming);
        cudaEventCreateWithFlags(&evJ, cudaEventDisableTiming);
    }

    const int TB = 256;
    int gE4 = (NE / 4 + TB - 1) / TB;
    const int GATHER_GRID = 1184;   // 8 blocks/SM, work-stealing
    const int MMA_GRID = 296;

    // CSR build; gemm1 needs dinv -> fork after scan, overlapping fill
    k_count<<<gE4, TB>>>(ei);
    k_scan<<<SCAN_B, 1024>>>();
    cudaEventRecord(evS, 0);
    cudaStreamWaitEvent(s2, evS, 0);
    k_gemm_mma<64, float, __half, false, true><<<MMA_GRID, 256, 0, s2>>>(x, W1, nullptr, bufh);
    cudaEventRecord(evJ, s2);
    k_fill<<<gE4, TB>>>(ei);

    // join, then alternate gather / HMMA GEMM
    cudaStreamWaitEvent(0, evJ, 0);
    k_gather<<<GATHER_GRID, 256>>>((const uint4*)bufh, b1, (uint4*)buf2, 0);
    k_gemm_mma<64, __half, __half, false, true><<<MMA_GRID, 256>>>(buf2, W2, nullptr, bufh);
    k_gather<<<GATHER_GRID, 256>>>((const uint4*)bufh, b2, (uint4*)buf2, 1);
    k_gemm_mma<32, __half, float, true, false><<<MMA_GRID, 256>>>(buf2, Wl, bl, out);
}

// round 17
// speedup vs baseline: 1.2923x; 1.2923x over previous
#include <cuda_runtime.h>
#include <cuda_fp16.h>
#include <cstdint>

#define NN 100000
#define NE 1200000
#define SCAN_B 98   // ceil(NN / 1024)

// ---------------- device scratch (no allocations allowed) ----------------
__device__ int                g_cnt[NN];
__device__ float              g_dinv[NN];
__device__ int                g_rowptr[NN + 1];
__device__ unsigned short     g_rank16[NE];
__device__ int                g_col[NE];
__device__ unsigned long long g_bval[SCAN_B];
__device__ __half             g_bufh[NN * 64];
__device__ __half             g_buf2[NN * 64];

// HMMA m16n8k16 row.col f32 accumulate
#define MMA_16816(c0, c1, c2, c3, a0, a1, a2, a3, b0, b1) \
    asm volatile("mma.sync.aligned.m16n8k16.row.col.f32.f16.f16.f32 " \
        "{%0,%1,%2,%3}, {%4,%5,%6,%7}, {%8,%9}, {%0,%1,%2,%3};" \
        : "+f"(c0), "+f"(c1), "+f"(c2), "+f"(c3) \
        : "r"(a0), "r"(a1), "r"(a2), "r"(a3), "r"(b0), "r"(b1))

// ---------------- per-block dtype probe ----------------
__device__ __forceinline__ int probe_is64(const int* __restrict__ raw) {
    __shared__ int s_is64;
    if (threadIdx.x < 32) {
        bool ok = true;
#pragma unroll
        for (int k = 0; k < 4; k++) {
            int idx = threadIdx.x * 4 + k;
            ok &= (raw[2 * idx + 1] == 0) && ((unsigned)raw[2 * idx] < NN);
        }
        unsigned m = __ballot_sync(~0u, ok);
        if (threadIdx.x == 0) s_is64 = (m == ~0u) ? 1 : 0;
    }
    __syncthreads();
    return s_is64;
}

// load edge pair [2*e2, 2*e2+1] from stream starting at word index base
__device__ __forceinline__ int2 edge_pair(const int* __restrict__ raw,
                                          long long base, int e2, int is64) {
    if (is64) {
        longlong2 v = __ldg((const longlong2*)((const long long*)raw + base + 2 * e2));
        return make_int2((int)v.x, (int)v.y);
    }
    return __ldg((const int2*)(raw + base + 2 * e2));
}

// ---------------- count + rank: 2 edges per thread ----------------
__global__ void k_count(const int* __restrict__ raw) {
    int is64 = probe_is64(raw);
    int e2 = blockIdx.x * blockDim.x + threadIdx.x;
    if (e2 >= NE / 2) return;
    int2 d = edge_pair(raw, NE, e2, is64);
    unsigned r0 = 0, r1 = 0;
    if ((unsigned)d.x < NN) r0 = (unsigned)atomicAdd(&g_cnt[d.x], 1);
    if ((unsigned)d.y < NN) r1 = (unsigned)atomicAdd(&g_cnt[d.y], 1);
    ((unsigned*)g_rank16)[e2] = (r0 & 0xFFFFu) | (r1 << 16);
}

// ---------------- single-kernel scan (decoupled lookback) ----------------
__global__ void __launch_bounds__(1024) k_scan() {
    __shared__ int wsum[32];
    __shared__ int s_boff;
    int tid = threadIdx.x;
    int lane = tid & 31, wid = tid >> 5;
    int i = blockIdx.x * 1024 + tid;
    int c = (i < NN) ? g_cnt[i] : 0;
    if (i < NN) {
        g_dinv[i] = rsqrtf((float)c + 1.0f);
        g_cnt[i] = 0;
    }
    int incl = c;
#pragma unroll
    for (int o = 1; o < 32; o <<= 1) {
        int t = __shfl_up_sync(~0u, incl, o);
        if (lane >= o) incl += t;
    }
    if (lane == 31) wsum[wid] = incl;
    __syncthreads();
    if (tid < 32) {
        int w = wsum[tid];
        int iw = w;
#pragma unroll
        for (int o = 1; o < 32; o <<= 1) {
            int t = __shfl_up_sync(~0u, iw, o);
            if (tid >= o) iw += t;
        }
        wsum[tid] = iw - w;
        if (tid == 31)
            atomicExch(&g_bval[blockIdx.x], (1ull << 32) | (unsigned)iw);
    }
    __syncthreads();
    if (wid == 0) {
        int my = blockIdx.x;
        unsigned acc = 0;
        for (int base = 0; base < my; base += 32) {
            int j = base + lane;
            if (j < my) {
                unsigned long long v;
                do { v = atomicAdd(&g_bval[j], 0ull); } while ((v >> 32) == 0);
                acc += (unsigned)v;
            }
        }
#pragma unroll
        for (int o = 16; o; o >>= 1) acc += __shfl_down_sync(~0u, acc, o);
        if (lane == 0) s_boff = (int)acc;
    }
    __syncthreads();
    if (i < NN) g_rowptr[i] = incl - c + wsum[wid] + s_boff;
    if (blockIdx.x == 0 && tid == 0) g_rowptr[NN] = NE;
}

// ---------------- fill CSR: 2 edges per thread, atomic-free ----------------
__global__ void k_fill(const int* __restrict__ raw) {
    int is64 = probe_is64(raw);
    if (blockIdx.x == 0 && threadIdx.x < SCAN_B) g_bval[threadIdx.x] = 0ull;
    int e2 = blockIdx.x * blockDim.x + threadIdx.x;
    if (e2 >= NE / 2) return;
    int2 s = edge_pair(raw, 0, e2, is64);
    int2 d = edge_pair(raw, NE, e2, is64);
    unsigned rr = ((const unsigned*)g_rank16)[e2];
    if ((unsigned)s.x < NN && (unsigned)d.x < NN)
        g_col[g_rowptr[d.x] + (int)(rr & 0xFFFFu)] = s.x;
    if ((unsigned)s.y < NN && (unsigned)d.y < NN)
        g_col[g_rowptr[d.y] + (int)(rr >> 16)] = s.y;
}

// ---------------- HMMA GEMM: out[N,NC] = X[N,64] @ W[64,NC] ----------------
// 8 warps x 16-row tiles = 128 rows/block. B fragments (m16n8k16 row.col
// layout) precomputed in SMEM; fp32 accumulate; fused dinv-scale / bias.
// InT = float (converted to fp16 in staging) or __half.
template <int NC, typename InT, typename OutT, bool BIAS, bool SCALE>
__global__ void __launch_bounds__(256) k_gemm_mma(const InT* __restrict__ in,
                                                  const float* __restrict__ W,
                                                  const float* __restrict__ bias,
                                                  OutT* __restrict__ out) {
    constexpr int NT = NC / 8;                 // n-tiles (8 or 4)
    constexpr int XS = 36;                     // row stride in u32 (64 halves + pad)
    __shared__ uint32_t Bf[4][NT][32][2];      // [ktile][ntile][lane][reg]
    __shared__ uint32_t Xs[128 * XS];

    int tid = threadIdx.x;
    int wid = tid >> 5, lane = tid & 31;
    int grp = lane >> 2;                       // 0..7
    int q   = lane & 3;                        // 0..3

    // Precompute B fragments: b_reg holds halves (k0, k0+1) at column n.
    for (int i = tid; i < 4 * NT * 32 * 2; i += 256) {
        int reg = i & 1;
        int ln  = (i >> 1) & 31;
        int nt  = (i >> 6) % NT;
        int kt  = (i >> 6) / NT;
        int k0 = kt * 16 + (ln & 3) * 2 + reg * 8;
        int n  = nt * 8 + (ln >> 2);
        __half2 h = __floats2half2_rn(W[k0 * NC + n], W[(k0 + 1) * NC + n]);
        Bf[kt][nt][ln][reg] = *(uint32_t*)&h;
    }

    int ntiles = (NN + 127) / 128;
    for (int tile = blockIdx.x; tile < ntiles; tile += gridDim.x) {
        int row0 = tile * 128;
        __syncthreads();
        for (int i = tid; i < 128 * 32; i += 256) {
            int r = i >> 5, c = i & 31;
            uint32_t v = 0;
            if (row0 + r < NN) {
                if constexpr (sizeof(InT) == 4) {
                    float2 f = __ldg((const float2*)in + (size_t)(row0 + r) * 32 + c);
                    __half2 h = __floats2half2_rn(f.x, f.y);
                    v = *(uint32_t*)&h;
                } else {
                    v = __ldg((const uint32_t*)in + (size_t)(row0 + r) * 32 + c);
                }
            }
            Xs[r * XS + c] = v;
        }
        __syncthreads();

        int rb = wid * 16;                     // warp's rows within tile
        float acc[NT][4];
#pragma unroll
        for (int nt = 0; nt < NT; nt++)
#pragma unroll
            for (int c = 0; c < 4; c++) acc[nt][c] = 0.f;

#pragma unroll
        for (int kt = 0; kt < 4; kt++) {
            uint32_t a0 = Xs[(rb + grp) * XS + kt * 8 + q];
            uint32_t a1 = Xs[(rb + grp + 8) * XS + kt * 8 + q];
            uint32_t a2 = Xs[(rb + grp) * XS + kt * 8 + 4 + q];
            uint32_t a3 = Xs[(rb + grp + 8) * XS + kt * 8 + 4 + q];
#pragma unroll
            for (int nt = 0; nt < NT; nt++) {
                uint32_t b0 = Bf[kt][nt][lane][0];
                uint32_t b1 = Bf[kt][nt][lane][1];
                MMA_16816(acc[nt][0], acc[nt][1], acc[nt][2], acc[nt][3],
                          a0, a1, a2, a3, b0, b1);
            }
        }

        int r0 = row0 + rb + grp;
        int r1 = r0 + 8;
        if constexpr (NC == 64) {
            float dv0 = (r0 < NN) ? __ldg(&g_dinv[r0]) : 0.f;
            float dv1 = (r1 < NN) ? __ldg(&g_dinv[r1]) : 0.f;
            if (!SCALE) { dv0 = 1.f; dv1 = 1.f; }
#pragma unroll
            for (int nt = 0; nt < NT; nt++) {
                int col = nt * 8 + q * 2;
                if (r0 < NN)
                    *(__half2*)((__half*)out + (size_t)r0 * NC + col) =
                        __floats2half2_rn(acc[nt][0] * dv0, acc[nt][1] * dv0);
                if (r1 < NN)
                    *(__half2*)((__half*)out + (size_t)r1 * NC + col) =
                        __floats2half2_rn(acc[nt][2] * dv1, acc[nt][3] * dv1);
            }
        } else {
#pragma unroll
            for (int nt = 0; nt < NT; nt++) {
                int col = nt * 8 + q * 2;
                float b0v = 0.f, b1v = 0.f;
                if (BIAS) { b0v = __ldg(&bias[col]); b1v = __ldg(&bias[col + 1]); }
                if (r0 < NN)
                    *(float2*)((float*)out + (size_t)r0 * NC + col) =
                        make_float2(acc[nt][0] + b0v, acc[nt][1] + b1v);
                if (r1 < NN)
                    *(float2*)((float*)out + (size_t)r1 * NC + col) =
                        make_float2(acc[nt][2] + b0v, acc[nt][3] + b1v);
            }
        }
    }
}

// ---------------- gather: 4 nodes/warp, 8 lanes x 8 dims ----------------
__global__ void __launch_bounds__(256) k_gather(const uint4* __restrict__ hw,
                                                const float* __restrict__ bias,
                                                uint4* __restrict__ hout) {
    int wrp  = blockIdx.x * 8 + (threadIdx.x >> 5);
    if (wrp * 4 >= NN) return;
    int lane = threadIdx.x & 31;
    int sub  = lane & 7;
    int node = wrp * 4 + (lane >> 3);

    uint4 sv = __ldg(&hw[node * 8 + sub]);
    float2 s0 = __half22float2(*(__half2*)&sv.x);
    float2 s1 = __half22float2(*(__half2*)&sv.y);
    float2 s2 = __half22float2(*(__half2*)&sv.z);
    float2 s3 = __half22float2(*(__half2*)&sv.w);
    float a0 = s0.x, a1 = s0.y, a2 = s1.x, a3 = s1.y;
    float a4 = s2.x, a5 = s2.y, a6 = s3.x, a7 = s3.y;

    int j   = g_rowptr[node];
    int end = g_rowptr[node + 1];
    while (__any_sync(~0u, j < end)) {
#pragma unroll
        for (int k = 0; k < 4; k++) {
            bool act = j < end;
            int jj = act ? j : 0;
            int c = __ldg(&g_col[jj]);
            float m = act ? 1.0f : 0.0f;
            uint4 u = __ldg(&hw[c * 8 + sub]);
            float2 g0 = __half22float2(*(__half2*)&u.x);
            float2 g1 = __half22float2(*(__half2*)&u.y);
            float2 g2 = __half22float2(*(__half2*)&u.z);
            float2 g3 = __half22float2(*(__half2*)&u.w);
            a0 = fmaf(m, g0.x, a0); a1 = fmaf(m, g0.y, a1);
            a2 = fmaf(m, g1.x, a2); a3 = fmaf(m, g1.y, a3);
            a4 = fmaf(m, g2.x, a4); a5 = fmaf(m, g2.y, a5);
            a6 = fmaf(m, g3.x, a6); a7 = fmaf(m, g3.y, a7);
            j++;
        }
    }

    float dv = __ldg(&g_dinv[node]);
    const float4* b4 = (const float4*)bias;
    float4 bl = b4[2 * sub], bh = b4[2 * sub + 1];
    a0 = fmaxf(fmaf(a0, dv, bl.x), 0.f);
    a1 = fmaxf(fmaf(a1, dv, bl.y), 0.f);
    a2 = fmaxf(fmaf(a2, dv, bl.z), 0.f);
    a3 = fmaxf(fmaf(a3, dv, bl.w), 0.f);
    a4 = fmaxf(fmaf(a4, dv, bh.x), 0.f);
    a5 = fmaxf(fmaf(a5, dv, bh.y), 0.f);
    a6 = fmaxf(fmaf(a6, dv, bh.z), 0.f);
    a7 = fmaxf(fmaf(a7, dv, bh.w), 0.f);
    uint4 o;
    *(__half2*)&o.x = __floats2half2_rn(a0, a1);
    *(__half2*)&o.y = __floats2half2_rn(a2, a3);
    *(__half2*)&o.z = __floats2half2_rn(a4, a5);
    *(__half2*)&o.w = __floats2half2_rn(a6, a7);
    hout[node * 8 + sub] = o;
}

// ---------------- launch ----------------
extern "C" void kernel_launch(void* const* d_in, const int* in_sizes, int n_in,
                              void* d_out, int out_size) {
    const float* x  = (const float*)d_in[0];
    const int*   ei = (const int*)d_in[1];
    const float* W1 = (const float*)d_in[2];
    const float* b1 = (const float*)d_in[3];
    const float* W2 = (const float*)d_in[4];
    const float* b2 = (const float*)d_in[5];
    const float* Wl = (const float*)d_in[6];
    const float* bl = (const float*)d_in[7];
    float*       out = (float*)d_out;

    __half* bufh; cudaGetSymbolAddress((void**)&bufh, g_bufh);
    __half* buf2; cudaGetSymbolAddress((void**)&buf2, g_buf2);

    static cudaStream_t s2 = nullptr;
    static cudaEvent_t evS = nullptr, evJ = nullptr;
    if (s2 == nullptr) {
        cudaStreamCreateWithFlags(&s2, cudaStreamNonBlocking);
        cudaEventCreateWithFlags(&evS, cudaEventDisableTiming);
        cudaEventCreateWithFlags(&evJ, cudaEventDisableTiming);
    }

    const int TB = 256;
    int gE2 = (NE / 2 + TB - 1) / TB;
    const int GATHER_GRID = (NN / 4 + 7) / 8;
    const int MMA_GRID = 296;

    // CSR build; gemm1 needs dinv -> fork after scan, overlapping fill
    k_count<<<gE2, TB>>>(ei);
    k_scan<<<SCAN_B, 1024>>>();
    cudaEventRecord(evS, 0);
    cudaStreamWaitEvent(s2, evS, 0);
    k_gemm_mma<64, float, __half, false, true><<<MMA_GRID, 256, 0, s2>>>(x, W1, nullptr, bufh);
    cudaEventRecord(evJ, s2);
    k_fill<<<gE2, TB>>>(ei);

    // join, then alternate gather / HMMA GEMM
    cudaStreamWaitEvent(0, evJ, 0);
    k_gather<<<GATHER_GRID, 256>>>((const uint4*)bufh, b1, (uint4*)buf2);
    k_gemm_mma<64, __half, __half, false, true><<<MMA_GRID, 256>>>(buf2, W2, nullptr, bufh);
    k_gather<<<GATHER_GRID, 256>>>((const uint4*)bufh, b2, (uint4*)buf2);
    k_gemm_mma<32, __half, float, true, false><<<MMA_GRID, 256>>>(buf2, Wl, bl, out);
}